// round 1
// baseline (speedup 1.0000x reference)
#include <cuda_runtime.h>

// Detail loss on GB300:
//   loss = mean|conv_h(infer)-conv_h(ref)| /2 + mean|conv_v(...)|/2
// Simplified: D = sum_c (infer - ref); Gh = 0.5*(D[w+1]-D[w-1]); Gv = 0.5*(D[h+1]-D[h-1])
// (zero padding at edges). Both means have identical denominators N*3*(H+2)*W
// since H==W, and the 3 identical output channels cancel, so:
//   out = (sum|Dw+1-Dw-1| + sum|Dh+1-Dh-1|) * 0.25 / (N*(H+2)*W)

#define NIMG 98          // 2*7*7
#define IMG_H 256
#define IMG_W 256
#define ROWS 32          // rows of D per block
#define STRIPS (IMG_H / ROWS)          // 8
#define NBLOCKS (NIMG * STRIPS)        // 784
#define PLANE (IMG_H * IMG_W)          // 65536

__device__ float g_block_sums[NBLOCKS];

__global__ void __launch_bounds__(256, 4)
detail_main(const float* __restrict__ infer, const float* __restrict__ ref) {
    __shared__ float Dsh[(ROWS + 2) * IMG_W];

    const int blk   = blockIdx.x;
    const int n     = blk / STRIPS;
    const int strip = blk % STRIPS;
    const int r0    = strip * ROWS;
    const int tid   = threadIdx.x;

    const float* pi = infer + (size_t)n * 3 * PLANE;
    const float* pr = ref   + (size_t)n * 3 * PLANE;

    // Load (ROWS+2) rows of D = sum_c (infer - ref) into shared; zero outside image.
    const int V4 = IMG_W / 4;  // 64 float4 per row
    #pragma unroll 1
    for (int idx = tid; idx < (ROWS + 2) * V4; idx += 256) {
        const int row = idx / V4;
        const int c4  = idx % V4;
        const int gh  = r0 - 1 + row;
        float4 d = make_float4(0.f, 0.f, 0.f, 0.f);
        if (gh >= 0 && gh < IMG_H) {
            const size_t off = (size_t)gh * IMG_W + c4 * 4;
            #pragma unroll
            for (int c = 0; c < 3; c++) {
                const float4 a = *(const float4*)(pi + (size_t)c * PLANE + off);
                const float4 b = *(const float4*)(pr + (size_t)c * PLANE + off);
                d.x += a.x - b.x;
                d.y += a.y - b.y;
                d.z += a.z - b.z;
                d.w += a.w - b.w;
            }
        }
        *(float4*)(Dsh + row * IMG_W + c4 * 4) = d;
    }
    __syncthreads();

    // Each thread owns one column; walk the ROWS interior rows.
    const int w = tid;
    float sum = 0.f;
    #pragma unroll 8
    for (int h = 0; h < ROWS; h++) {
        const float* rowm = Dsh + h * IMG_W;         // h-1 (global)
        const float* rowc = rowm + IMG_W;            // h
        const float* rowp = rowc + IMG_W;            // h+1
        const float l = (w > 0)         ? rowc[w - 1] : 0.f;
        const float r = (w < IMG_W - 1) ? rowc[w + 1] : 0.f;
        sum += fabsf(r - l);                 // horizontal gradient (x0.5 folded out)
        sum += fabsf(rowp[w] - rowm[w]);     // vertical gradient
    }

    // Block reduction
    #pragma unroll
    for (int off = 16; off > 0; off >>= 1)
        sum += __shfl_down_sync(0xffffffffu, sum, off);
    __shared__ float wsum[8];
    if ((tid & 31) == 0) wsum[tid >> 5] = sum;
    __syncthreads();
    if (tid < 32) {
        float s = (tid < 8) ? wsum[tid] : 0.f;
        #pragma unroll
        for (int off = 4; off > 0; off >>= 1)
            s += __shfl_down_sync(0xffffffffu, s, off);
        if (tid == 0) g_block_sums[blk] = s;
    }
}

__global__ void __launch_bounds__(256)
detail_finalize(float* __restrict__ out) {
    const int tid = threadIdx.x;
    float s = 0.f;
    for (int i = tid; i < NBLOCKS; i += 256) s += g_block_sums[i];
    #pragma unroll
    for (int off = 16; off > 0; off >>= 1)
        s += __shfl_down_sync(0xffffffffu, s, off);
    __shared__ float wsum[8];
    if ((tid & 31) == 0) wsum[tid >> 5] = s;
    __syncthreads();
    if (tid == 0) {
        float t = 0.f;
        #pragma unroll
        for (int i = 0; i < 8; i++) t += wsum[i];
        // scale = 0.5 (gradient coeff) * 0.5 (avg of two losses) / (98*258*256)
        out[0] = t * (0.25f / 6472704.0f);
    }
}

extern "C" void kernel_launch(void* const* d_in, const int* in_sizes, int n_in,
                              void* d_out, int out_size) {
    const float* infer = (const float*)d_in[0];
    const float* ref   = (const float*)d_in[1];
    float* out = (float*)d_out;

    detail_main<<<NBLOCKS, 256>>>(infer, ref);
    detail_finalize<<<1, 256>>>(out);
}